// round 1
// baseline (speedup 1.0000x reference)
#include <cuda_runtime.h>
#include <cuda_bf16.h>
#include <math.h>

// Problem constants
#define BB 2
#define SS 2048
#define DD 1024
#define HH 16
#define DKK 64
#define MM (BB * SS)   // 4096 rows for all GEMMs

// ---------------------------------------------------------------------------
// Scratch (device globals; no runtime allocation allowed)
// ---------------------------------------------------------------------------
__device__ float g_Q[BB * HH * SS * DKK];   // [B,H,S,DK]
__device__ float g_K[BB * HH * SS * DKK];
__device__ float g_V[BB * HH * SS * DKK];
__device__ float g_Ctx[BB * SS * DD];       // [B,S,D] attention output

// ---------------------------------------------------------------------------
// NT GEMM: C[m,n] = sum_k A[m,k] * W[n,k] + bias[n]
// M=4096, N=1024, K=1024 fixed. BM=BN=128, BK=16, 256 threads, 8x8/thread.
// out_mode: 0 -> write C[m*N+n] (plain row-major)
//           1/2/3 -> scatter to g_Q/g_K/g_V in [B,H,S,DK] layout
// in_mode:  0 -> read A argument; 1 -> read g_Ctx
// ---------------------------------------------------------------------------
__global__ __launch_bounds__(256) void gemm_nt_kernel(
    const float* __restrict__ A, const float* __restrict__ W,
    const float* __restrict__ bias, float* __restrict__ C,
    int out_mode, int in_mode)
{
    const int Mc = MM, Nc = DD, Kc = DD;
    const int BM = 128, BN = 128, BK = 16;

    __shared__ float As[BK][BM + 4];
    __shared__ float Bs[BK][BN + 4];

    const float* __restrict__ Ain = (in_mode == 1) ? (const float*)g_Ctx : A;

    int tid = threadIdx.x;
    int tx = tid & 15;       // N-dim thread coord
    int ty = tid >> 4;       // M-dim thread coord
    int bm = blockIdx.y * BM;
    int bn = blockIdx.x * BN;

    int lrow = tid >> 2;           // 0..63
    int lc4  = (tid & 3) << 2;     // 0,4,8,12

    float acc[8][8];
#pragma unroll
    for (int i = 0; i < 8; i++)
#pragma unroll
        for (int j = 0; j < 8; j++) acc[i][j] = 0.0f;

    for (int k0 = 0; k0 < Kc; k0 += BK) {
#pragma unroll
        for (int half = 0; half < 2; half++) {
            int r = lrow + half * 64;
            float4 va = *(const float4*)&Ain[(size_t)(bm + r) * Kc + k0 + lc4];
            As[lc4 + 0][r] = va.x;
            As[lc4 + 1][r] = va.y;
            As[lc4 + 2][r] = va.z;
            As[lc4 + 3][r] = va.w;
            float4 vb = *(const float4*)&W[(size_t)(bn + r) * Kc + k0 + lc4];
            Bs[lc4 + 0][r] = vb.x;
            Bs[lc4 + 1][r] = vb.y;
            Bs[lc4 + 2][r] = vb.z;
            Bs[lc4 + 3][r] = vb.w;
        }
        __syncthreads();

#pragma unroll
        for (int kk = 0; kk < BK; kk++) {
            float4 a0 = *(const float4*)&As[kk][ty * 8];
            float4 a1 = *(const float4*)&As[kk][ty * 8 + 4];
            float4 b0 = *(const float4*)&Bs[kk][tx * 8];
            float4 b1 = *(const float4*)&Bs[kk][tx * 8 + 4];
            float a[8] = {a0.x, a0.y, a0.z, a0.w, a1.x, a1.y, a1.z, a1.w};
            float b[8] = {b0.x, b0.y, b0.z, b0.w, b1.x, b1.y, b1.z, b1.w};
#pragma unroll
            for (int i = 0; i < 8; i++)
#pragma unroll
                for (int j = 0; j < 8; j++) acc[i][j] = fmaf(a[i], b[j], acc[i][j]);
        }
        __syncthreads();
    }

    // epilogue
#pragma unroll
    for (int i = 0; i < 8; i++) {
        int m = bm + ty * 8 + i;
#pragma unroll
        for (int j = 0; j < 8; j++) {
            int n = bn + tx * 8 + j;
            float v = acc[i][j] + bias[n];
            if (out_mode == 0) {
                C[(size_t)m * Nc + n] = v;
            } else {
                int b = m >> 11;          // m / S
                int s = m & (SS - 1);     // m % S
                int h = n >> 6;           // n / DK
                int dk = n & (DKK - 1);   // n % DK
                float* dst = (out_mode == 1) ? g_Q : (out_mode == 2) ? g_K : g_V;
                dst[(((size_t)(b * HH + h)) * SS + s) * DKK + dk] = v;
            }
        }
    }
}

// ---------------------------------------------------------------------------
// Causal flash attention, fp32.
// grid.x = S/BQ (query block), grid.y = B*H. 256 threads (16x16).
// BQ=64 queries, BKT=32 keys per iteration, DK=64.
// Thread (ty,tx): score tile rows ty*4..+3, score cols tx*2..+1,
//                 O tile   rows ty*4..+3, O cols    tx*4..+3.
// ---------------------------------------------------------------------------
__global__ __launch_bounds__(256) void attn_kernel()
{
    const int BQ = 64, BKT = 32;
    const float scale = 0.125f;  // 1/sqrt(64)

    __shared__ float Qs[BQ][65];     // 16640 B
    __shared__ float Ks[BKT][65];    //  8320 B
    __shared__ float Vs[BKT][68];    //  8704 B (68: 16B-aligned float4 reads)
    __shared__ float Ps[BQ][33];     //  8448 B

    int tid = threadIdx.x;
    int tx = tid & 15;
    int ty = tid >> 4;
    int r0 = ty * 4;

    int qb = blockIdx.x;                 // query block
    int bh = blockIdx.y;                 // b*H + h
    int b  = bh >> 4;
    int h  = bh & (HH - 1);

    size_t head_base = (size_t)bh * SS * DKK;

    // load Q tile [64][64]
    for (int idx = tid; idx < BQ * DKK; idx += 256) {
        int r = idx >> 6, c = idx & 63;
        Qs[r][c] = g_Q[head_base + (size_t)(qb * BQ + r) * DKK + c];
    }

    float m_i[4], l_i[4], o[4][4];
#pragma unroll
    for (int i = 0; i < 4; i++) {
        m_i[i] = -1e30f;
        l_i[i] = 0.0f;
#pragma unroll
        for (int j = 0; j < 4; j++) o[i][j] = 0.0f;
    }

    int jmax = 2 * qb + 1;  // inclusive; BKT*(2qb+1)+31 = 64qb+63 = last query of block
    for (int j = 0; j <= jmax; j++) {
        __syncthreads();
        // load K,V tiles [32][64]
        for (int idx = tid; idx < BKT * DKK; idx += 256) {
            int r = idx >> 6, c = idx & 63;
            size_t g = head_base + (size_t)(j * BKT + r) * DKK + c;
            Ks[r][c] = g_K[g];
            Vs[r][c] = g_V[g];
        }
        __syncthreads();

        // scores: s[i][c] = sum_d Qs[r0+i][d] * Ks[2tx+c][d]
        float s0[4], s1[4];
#pragma unroll
        for (int i = 0; i < 4; i++) { s0[i] = 0.0f; s1[i] = 0.0f; }
#pragma unroll 8
        for (int d = 0; d < DKK; d++) {
            float kv0 = Ks[2 * tx][d];
            float kv1 = Ks[2 * tx + 1][d];
#pragma unroll
            for (int i = 0; i < 4; i++) {
                float qv = Qs[r0 + i][d];
                s0[i] = fmaf(qv, kv0, s0[i]);
                s1[i] = fmaf(qv, kv1, s1[i]);
            }
        }

        int kj0 = j * BKT + 2 * tx;
        int kj1 = kj0 + 1;
#pragma unroll
        for (int i = 0; i < 4; i++) {
            int qi = qb * BQ + r0 + i;
            float v0 = (kj0 <= qi) ? s0[i] * scale : -1e9f;
            float v1 = (kj1 <= qi) ? s1[i] * scale : -1e9f;

            // row max across 16 tx lanes
            float mx = fmaxf(v0, v1);
#pragma unroll
            for (int off = 8; off > 0; off >>= 1)
                mx = fmaxf(mx, __shfl_xor_sync(0xffffffffu, mx, off, 16));
            float mnew = fmaxf(m_i[i], mx);

            float p0 = __expf(v0 - mnew);
            float p1 = __expf(v1 - mnew);
            float rs = p0 + p1;
#pragma unroll
            for (int off = 8; off > 0; off >>= 1)
                rs += __shfl_xor_sync(0xffffffffu, rs, off, 16);

            float alpha = __expf(m_i[i] - mnew);
            l_i[i] = l_i[i] * alpha + rs;
            m_i[i] = mnew;
#pragma unroll
            for (int jj = 0; jj < 4; jj++) o[i][jj] *= alpha;

            Ps[r0 + i][2 * tx]     = p0;
            Ps[r0 + i][2 * tx + 1] = p1;
        }
        __syncthreads();

        // O += P @ V   (P: [64][32], V: [32][64])
#pragma unroll 4
        for (int kk = 0; kk < BKT; kk++) {
            float4 vv = *(const float4*)&Vs[kk][tx * 4];
#pragma unroll
            for (int i = 0; i < 4; i++) {
                float pp = Ps[r0 + i][kk];
                o[i][0] = fmaf(pp, vv.x, o[i][0]);
                o[i][1] = fmaf(pp, vv.y, o[i][1]);
                o[i][2] = fmaf(pp, vv.z, o[i][2]);
                o[i][3] = fmaf(pp, vv.w, o[i][3]);
            }
        }
    }

    // write out in [B,S,D] layout: g_Ctx[(b*S+s)*D + h*DK + col]
#pragma unroll
    for (int i = 0; i < 4; i++) {
        float inv = 1.0f / l_i[i];
        int s = qb * BQ + r0 + i;
        size_t base = ((size_t)(b * SS + s)) * DD + h * DKK + tx * 4;
#pragma unroll
        for (int jj = 0; jj < 4; jj++)
            g_Ctx[base + jj] = o[i][jj] * inv;
    }
}

// ---------------------------------------------------------------------------
// kernel_launch
// inputs: 0 q, 1 k, 2 v, 3 mask(unused, known tril), 4 wq_w, 5 wq_b,
//         6 wk_w, 7 wk_b, 8 wv_w, 9 wv_b, 10 wo_w, 11 wo_b
// output: [B,S,D] float32
// ---------------------------------------------------------------------------
extern "C" void kernel_launch(void* const* d_in, const int* in_sizes, int n_in,
                              void* d_out, int out_size)
{
    const float* q    = (const float*)d_in[0];
    const float* k    = (const float*)d_in[1];
    const float* v    = (const float*)d_in[2];
    const float* wq_w = (const float*)d_in[4];
    const float* wq_b = (const float*)d_in[5];
    const float* wk_w = (const float*)d_in[6];
    const float* wk_b = (const float*)d_in[7];
    const float* wv_w = (const float*)d_in[8];
    const float* wv_b = (const float*)d_in[9];
    const float* wo_w = (const float*)d_in[10];
    const float* wo_b = (const float*)d_in[11];
    float* out = (float*)d_out;

    dim3 gg(DD / 128, MM / 128);  // (8, 32)

    // QKV projections (scatter to [B,H,S,DK] scratch)
    gemm_nt_kernel<<<gg, 256>>>(q, wq_w, wq_b, nullptr, 1, 0);
    gemm_nt_kernel<<<gg, 256>>>(k, wk_w, wk_b, nullptr, 2, 0);
    gemm_nt_kernel<<<gg, 256>>>(v, wv_w, wv_b, nullptr, 3, 0);

    // causal attention -> g_Ctx [B,S,D]
    attn_kernel<<<dim3(SS / 64, BB * HH), 256>>>();

    // output projection
    gemm_nt_kernel<<<gg, 256>>>(nullptr, wo_w, wo_b, out, 0, 1);
}

// round 2
// speedup vs baseline: 1.2980x; 1.2980x over previous
#include <cuda_runtime.h>
#include <cuda_bf16.h>
#include <math.h>

// Problem constants
#define BB 2
#define SS 2048
#define DD 1024
#define HH 16
#define DKK 64
#define MM (BB * SS)   // 4096 rows for all GEMMs

// ---------------------------------------------------------------------------
// Scratch (device globals; no runtime allocation allowed)
// ---------------------------------------------------------------------------
__device__ float g_Q[BB * HH * SS * DKK];   // [B,H,S,DK]
__device__ float g_K[BB * HH * SS * DKK];
__device__ float g_V[BB * HH * SS * DKK];
__device__ float g_Ctx[BB * SS * DD];       // [B,S,D] attention output

// ---------------------------------------------------------------------------
// tf32 helpers
// ---------------------------------------------------------------------------
__device__ __forceinline__ unsigned f2tf32(float x) {
    unsigned y;
    asm("cvt.rna.tf32.f32 %0, %1;" : "=r"(y) : "f"(x));
    return y;
}

__device__ __forceinline__ void mma_tf32(float* c, const unsigned* a, const unsigned* b) {
    asm volatile("mma.sync.aligned.m16n8k8.row.col.f32.tf32.tf32.f32 "
        "{%0,%1,%2,%3}, {%4,%5,%6,%7}, {%8,%9}, {%0,%1,%2,%3};"
        : "+f"(c[0]), "+f"(c[1]), "+f"(c[2]), "+f"(c[3])
        : "r"(a[0]), "r"(a[1]), "r"(a[2]), "r"(a[3]), "r"(b[0]), "r"(b[1]));
}

// ---------------------------------------------------------------------------
// NT GEMM via tf32 tensor cores:
//   C[m,n] = sum_k Ain[m,k] * W[n,k] + bias[n]
// M=4096, N=1024, K=1024. BM=BN=128, BK=16, 256 threads (8 warps).
// Warp layout 2x4; each warp: 64x32 subtile = 4x4 m16n8k8 atoms.
// out_mode: 0 -> C[m*N+n]; 1/2/3 -> scatter to g_Q/g_K/g_V [B,H,S,DK]
// in_mode:  0 -> A argument; 1 -> g_Ctx
// ---------------------------------------------------------------------------
__global__ __launch_bounds__(256, 2) void gemm_tf32_kernel(
    const float* __restrict__ A, const float* __restrict__ W,
    const float* __restrict__ bias, float* __restrict__ C,
    int out_mode, int in_mode)
{
    const int Nc = DD, Kc = DD;

    // pad to 136 words: 136 mod 32 = 8 -> fragment LDS conflict-free
    __shared__ unsigned As[16][136];
    __shared__ unsigned Bs[16][136];

    const float* __restrict__ Ain = (in_mode == 1) ? (const float*)g_Ctx : A;

    int tid  = threadIdx.x;
    int lane = tid & 31;
    int w    = tid >> 5;
    int wm   = w >> 2;          // 0..1
    int wn   = w & 3;           // 0..3
    int g    = lane >> 2;       // 0..7
    int t    = lane & 3;        // 0..3

    int bm = blockIdx.y * 128;
    int bn = blockIdx.x * 128;

    float c[4][4][4];
#pragma unroll
    for (int mi = 0; mi < 4; mi++)
#pragma unroll
        for (int nj = 0; nj < 4; nj++)
#pragma unroll
            for (int e = 0; e < 4; e++) c[mi][nj][e] = 0.0f;

    for (int k0 = 0; k0 < Kc; k0 += 16) {
        // ---- stage tiles (conflict-free STS; lanes hit consecutive rows) ----
#pragma unroll
        for (int it = 0; it < 2; it++) {
            int idx = it * 256 + tid;
            int r   = (idx & 31) | ((idx >> 7) << 5);   // 0..127
            int c4  = ((idx >> 5) & 3) * 4;             // 0,4,8,12
            float4 va = *(const float4*)&Ain[(size_t)(bm + r) * Kc + k0 + c4];
            As[c4 + 0][r] = f2tf32(va.x);
            As[c4 + 1][r] = f2tf32(va.y);
            As[c4 + 2][r] = f2tf32(va.z);
            As[c4 + 3][r] = f2tf32(va.w);
            float4 vb = *(const float4*)&W[(size_t)(bn + r) * Kc + k0 + c4];
            Bs[c4 + 0][r] = f2tf32(vb.x);
            Bs[c4 + 1][r] = f2tf32(vb.y);
            Bs[c4 + 2][r] = f2tf32(vb.z);
            Bs[c4 + 3][r] = f2tf32(vb.w);
        }
        __syncthreads();

        // ---- compute: 2 k-steps of 8 ----
#pragma unroll
        for (int ks = 0; ks < 2; ks++) {
            unsigned af[4][4], bf[4][2];
#pragma unroll
            for (int mi = 0; mi < 4; mi++) {
                int m = wm * 64 + mi * 16 + g;
                af[mi][0] = As[ks * 8 + t][m];
                af[mi][1] = As[ks * 8 + t][m + 8];
                af[mi][2] = As[ks * 8 + t + 4][m];
                af[mi][3] = As[ks * 8 + t + 4][m + 8];
            }
#pragma unroll
            for (int nj = 0; nj < 4; nj++) {
                int n = wn * 32 + nj * 8 + g;
                bf[nj][0] = Bs[ks * 8 + t][n];
                bf[nj][1] = Bs[ks * 8 + t + 4][n];
            }
#pragma unroll
            for (int mi = 0; mi < 4; mi++)
#pragma unroll
                for (int nj = 0; nj < 4; nj++)
                    mma_tf32(c[mi][nj], af[mi], bf[nj]);
        }
        __syncthreads();
    }

    // ---- epilogue: bias + store (pairs are n-contiguous) ----
#pragma unroll
    for (int mi = 0; mi < 4; mi++) {
#pragma unroll
        for (int nj = 0; nj < 4; nj++) {
            int m = bm + wm * 64 + mi * 16 + g;
            int n = bn + wn * 32 + nj * 8 + 2 * t;
            float b0 = bias[n], b1 = bias[n + 1];
            float2 v0 = make_float2(c[mi][nj][0] + b0, c[mi][nj][1] + b1);
            float2 v1 = make_float2(c[mi][nj][2] + b0, c[mi][nj][3] + b1);
            if (out_mode == 0) {
                *(float2*)&C[(size_t)m * Nc + n]       = v0;
                *(float2*)&C[(size_t)(m + 8) * Nc + n] = v1;
            } else {
                int b  = m >> 11;
                int s  = m & (SS - 1);
                int h  = n >> 6;
                int dk = n & (DKK - 1);
                float* dst = (out_mode == 1) ? g_Q : (out_mode == 2) ? g_K : g_V;
                size_t base = (((size_t)(b * HH + h)) * SS) * DKK + dk;
                *(float2*)&dst[base + (size_t)s * DKK]       = v0;
                int s1 = (m + 8) & (SS - 1);
                *(float2*)&dst[base + (size_t)s1 * DKK]      = v1;
            }
        }
    }
}

// ---------------------------------------------------------------------------
// Causal flash attention, fp32 (unchanged from R0 baseline).
// ---------------------------------------------------------------------------
__global__ __launch_bounds__(256) void attn_kernel()
{
    const int BQ = 64, BKT = 32;
    const float scale = 0.125f;  // 1/sqrt(64)

    __shared__ float Qs[BQ][65];
    __shared__ float Ks[BKT][65];
    __shared__ float Vs[BKT][68];
    __shared__ float Ps[BQ][33];

    int tid = threadIdx.x;
    int tx = tid & 15;
    int ty = tid >> 4;
    int r0 = ty * 4;

    int qb = blockIdx.x;
    int bh = blockIdx.y;
    int b  = bh >> 4;
    int h  = bh & (HH - 1);

    size_t head_base = (size_t)bh * SS * DKK;

    for (int idx = tid; idx < BQ * DKK; idx += 256) {
        int r = idx >> 6, c = idx & 63;
        Qs[r][c] = g_Q[head_base + (size_t)(qb * BQ + r) * DKK + c];
    }

    float m_i[4], l_i[4], o[4][4];
#pragma unroll
    for (int i = 0; i < 4; i++) {
        m_i[i] = -1e30f;
        l_i[i] = 0.0f;
#pragma unroll
        for (int j = 0; j < 4; j++) o[i][j] = 0.0f;
    }

    int jmax = 2 * qb + 1;
    for (int j = 0; j <= jmax; j++) {
        __syncthreads();
        for (int idx = tid; idx < BKT * DKK; idx += 256) {
            int r = idx >> 6, c = idx & 63;
            size_t gg = head_base + (size_t)(j * BKT + r) * DKK + c;
            Ks[r][c] = g_K[gg];
            Vs[r][c] = g_V[gg];
        }
        __syncthreads();

        float s0[4], s1[4];
#pragma unroll
        for (int i = 0; i < 4; i++) { s0[i] = 0.0f; s1[i] = 0.0f; }
#pragma unroll 8
        for (int d = 0; d < DKK; d++) {
            float kv0 = Ks[2 * tx][d];
            float kv1 = Ks[2 * tx + 1][d];
#pragma unroll
            for (int i = 0; i < 4; i++) {
                float qv = Qs[r0 + i][d];
                s0[i] = fmaf(qv, kv0, s0[i]);
                s1[i] = fmaf(qv, kv1, s1[i]);
            }
        }

        int kj0 = j * BKT + 2 * tx;
        int kj1 = kj0 + 1;
#pragma unroll
        for (int i = 0; i < 4; i++) {
            int qi = qb * BQ + r0 + i;
            float v0 = (kj0 <= qi) ? s0[i] * scale : -1e9f;
            float v1 = (kj1 <= qi) ? s1[i] * scale : -1e9f;

            float mx = fmaxf(v0, v1);
#pragma unroll
            for (int off = 8; off > 0; off >>= 1)
                mx = fmaxf(mx, __shfl_xor_sync(0xffffffffu, mx, off, 16));
            float mnew = fmaxf(m_i[i], mx);

            float p0 = __expf(v0 - mnew);
            float p1 = __expf(v1 - mnew);
            float rs = p0 + p1;
#pragma unroll
            for (int off = 8; off > 0; off >>= 1)
                rs += __shfl_xor_sync(0xffffffffu, rs, off, 16);

            float alpha = __expf(m_i[i] - mnew);
            l_i[i] = l_i[i] * alpha + rs;
            m_i[i] = mnew;
#pragma unroll
            for (int jj = 0; jj < 4; jj++) o[i][jj] *= alpha;

            Ps[r0 + i][2 * tx]     = p0;
            Ps[r0 + i][2 * tx + 1] = p1;
        }
        __syncthreads();

#pragma unroll 4
        for (int kk = 0; kk < BKT; kk++) {
            float4 vv = *(const float4*)&Vs[kk][tx * 4];
#pragma unroll
            for (int i = 0; i < 4; i++) {
                float pp = Ps[r0 + i][kk];
                o[i][0] = fmaf(pp, vv.x, o[i][0]);
                o[i][1] = fmaf(pp, vv.y, o[i][1]);
                o[i][2] = fmaf(pp, vv.z, o[i][2]);
                o[i][3] = fmaf(pp, vv.w, o[i][3]);
            }
        }
    }

#pragma unroll
    for (int i = 0; i < 4; i++) {
        float inv = 1.0f / l_i[i];
        int s = qb * BQ + r0 + i;
        size_t base = ((size_t)(b * SS + s)) * DD + h * DKK + tx * 4;
#pragma unroll
        for (int jj = 0; jj < 4; jj++)
            g_Ctx[base + jj] = o[i][jj] * inv;
    }
}

// ---------------------------------------------------------------------------
// kernel_launch
// ---------------------------------------------------------------------------
extern "C" void kernel_launch(void* const* d_in, const int* in_sizes, int n_in,
                              void* d_out, int out_size)
{
    const float* q    = (const float*)d_in[0];
    const float* k    = (const float*)d_in[1];
    const float* v    = (const float*)d_in[2];
    const float* wq_w = (const float*)d_in[4];
    const float* wq_b = (const float*)d_in[5];
    const float* wk_w = (const float*)d_in[6];
    const float* wk_b = (const float*)d_in[7];
    const float* wv_w = (const float*)d_in[8];
    const float* wv_b = (const float*)d_in[9];
    const float* wo_w = (const float*)d_in[10];
    const float* wo_b = (const float*)d_in[11];
    float* out = (float*)d_out;

    dim3 gg(DD / 128, MM / 128);  // (8, 32)

    gemm_tf32_kernel<<<gg, 256>>>(q, wq_w, wq_b, nullptr, 1, 0);
    gemm_tf32_kernel<<<gg, 256>>>(k, wk_w, wk_b, nullptr, 2, 0);
    gemm_tf32_kernel<<<gg, 256>>>(v, wv_w, wv_b, nullptr, 3, 0);

    attn_kernel<<<dim3(SS / 64, BB * HH), 256>>>();

    gemm_tf32_kernel<<<gg, 256>>>(nullptr, wo_w, wo_b, out, 0, 1);
}

// round 3
// speedup vs baseline: 2.2015x; 1.6961x over previous
#include <cuda_runtime.h>
#include <cuda_bf16.h>
#include <math.h>

// Problem constants
#define BB 2
#define SS 2048
#define DD 1024
#define HH 16
#define DKK 64
#define MM (BB * SS)   // 4096 rows for all GEMMs

// ---------------------------------------------------------------------------
// Scratch (device globals; no runtime allocation allowed)
// ---------------------------------------------------------------------------
__device__ float g_Q[BB * HH * SS * DKK];   // [B,H,S,DK]
__device__ float g_K[BB * HH * SS * DKK];
__device__ float g_V[BB * HH * SS * DKK];
__device__ float g_Ctx[BB * SS * DD];       // [B,S,D] attention output

// ---------------------------------------------------------------------------
// tf32 helpers
// ---------------------------------------------------------------------------
__device__ __forceinline__ unsigned f2tf32(float x) {
    unsigned y;
    asm("cvt.rna.tf32.f32 %0, %1;" : "=r"(y) : "f"(x));
    return y;
}

__device__ __forceinline__ float ex2(float x) {
    float y;
    asm("ex2.approx.f32 %0, %1;" : "=f"(y) : "f"(x));
    return y;
}

__device__ __forceinline__ void mma_tf32(float* c, const unsigned* a, const unsigned* b) {
    asm volatile("mma.sync.aligned.m16n8k8.row.col.f32.tf32.tf32.f32 "
        "{%0,%1,%2,%3}, {%4,%5,%6,%7}, {%8,%9}, {%0,%1,%2,%3};"
        : "+f"(c[0]), "+f"(c[1]), "+f"(c[2]), "+f"(c[3])
        : "r"(a[0]), "r"(a[1]), "r"(a[2]), "r"(a[3]), "r"(b[0]), "r"(b[1]));
}

// ---------------------------------------------------------------------------
// NT GEMM via tf32 tensor cores (unchanged from R1):
//   C[m,n] = sum_k Ain[m,k] * W[n,k] + bias[n]
// ---------------------------------------------------------------------------
__global__ __launch_bounds__(256, 2) void gemm_tf32_kernel(
    const float* __restrict__ A, const float* __restrict__ W,
    const float* __restrict__ bias, float* __restrict__ C,
    int out_mode, int in_mode)
{
    const int Nc = DD, Kc = DD;

    __shared__ unsigned As[16][136];
    __shared__ unsigned Bs[16][136];

    const float* __restrict__ Ain = (in_mode == 1) ? (const float*)g_Ctx : A;

    int tid  = threadIdx.x;
    int lane = tid & 31;
    int w    = tid >> 5;
    int wm   = w >> 2;
    int wn   = w & 3;
    int g    = lane >> 2;
    int t    = lane & 3;

    int bm = blockIdx.y * 128;
    int bn = blockIdx.x * 128;

    float c[4][4][4];
#pragma unroll
    for (int mi = 0; mi < 4; mi++)
#pragma unroll
        for (int nj = 0; nj < 4; nj++)
#pragma unroll
            for (int e = 0; e < 4; e++) c[mi][nj][e] = 0.0f;

    for (int k0 = 0; k0 < Kc; k0 += 16) {
#pragma unroll
        for (int it = 0; it < 2; it++) {
            int idx = it * 256 + tid;
            int r   = (idx & 31) | ((idx >> 7) << 5);
            int c4  = ((idx >> 5) & 3) * 4;
            float4 va = *(const float4*)&Ain[(size_t)(bm + r) * Kc + k0 + c4];
            As[c4 + 0][r] = f2tf32(va.x);
            As[c4 + 1][r] = f2tf32(va.y);
            As[c4 + 2][r] = f2tf32(va.z);
            As[c4 + 3][r] = f2tf32(va.w);
            float4 vb = *(const float4*)&W[(size_t)(bn + r) * Kc + k0 + c4];
            Bs[c4 + 0][r] = f2tf32(vb.x);
            Bs[c4 + 1][r] = f2tf32(vb.y);
            Bs[c4 + 2][r] = f2tf32(vb.z);
            Bs[c4 + 3][r] = f2tf32(vb.w);
        }
        __syncthreads();

#pragma unroll
        for (int ks = 0; ks < 2; ks++) {
            unsigned af[4][4], bf[4][2];
#pragma unroll
            for (int mi = 0; mi < 4; mi++) {
                int m = wm * 64 + mi * 16 + g;
                af[mi][0] = As[ks * 8 + t][m];
                af[mi][1] = As[ks * 8 + t][m + 8];
                af[mi][2] = As[ks * 8 + t + 4][m];
                af[mi][3] = As[ks * 8 + t + 4][m + 8];
            }
#pragma unroll
            for (int nj = 0; nj < 4; nj++) {
                int n = wn * 32 + nj * 8 + g;
                bf[nj][0] = Bs[ks * 8 + t][n];
                bf[nj][1] = Bs[ks * 8 + t + 4][n];
            }
#pragma unroll
            for (int mi = 0; mi < 4; mi++)
#pragma unroll
                for (int nj = 0; nj < 4; nj++)
                    mma_tf32(c[mi][nj], af[mi], bf[nj]);
        }
        __syncthreads();
    }

#pragma unroll
    for (int mi = 0; mi < 4; mi++) {
#pragma unroll
        for (int nj = 0; nj < 4; nj++) {
            int m = bm + wm * 64 + mi * 16 + g;
            int n = bn + wn * 32 + nj * 8 + 2 * t;
            float b0 = bias[n], b1 = bias[n + 1];
            float2 v0 = make_float2(c[mi][nj][0] + b0, c[mi][nj][1] + b1);
            float2 v1 = make_float2(c[mi][nj][2] + b0, c[mi][nj][3] + b1);
            if (out_mode == 0) {
                *(float2*)&C[(size_t)m * Nc + n]       = v0;
                *(float2*)&C[(size_t)(m + 8) * Nc + n] = v1;
            } else {
                int b  = m >> 11;
                int s  = m & (SS - 1);
                int h  = n >> 6;
                int dk = n & (DKK - 1);
                float* dst = (out_mode == 1) ? g_Q : (out_mode == 2) ? g_K : g_V;
                size_t base = (((size_t)(b * HH + h)) * SS) * DKK + dk;
                *(float2*)&dst[base + (size_t)s * DKK]  = v0;
                int s1 = (m + 8) & (SS - 1);
                *(float2*)&dst[base + (size_t)s1 * DKK] = v1;
            }
        }
    }
}

// ---------------------------------------------------------------------------
// Causal flash attention via tf32 tensor cores.
// grid = (S/64, B*H), 128 threads (4 warps). Warp w owns Q rows [16w,16w+16).
// Per k-tile (64 keys): S = Q@K^T (64 mma/warp), streaming softmax on the
// accumulator layout, P -> smem (reusing Q's smem), O += P@V (64 mma/warp).
// ---------------------------------------------------------------------------
#define SCALE_LOG2E 0.1803368801111244f   // (1/sqrt(64)) * log2(e)

__global__ __launch_bounds__(128) void attn_tc_kernel()
{
    // QPs: Q tile first (frags go to registers), then reused for P
    __shared__ unsigned QPs[64][68];
    __shared__ unsigned Ks[64][68];
    __shared__ unsigned Vs[64][72];

    int tid  = threadIdx.x;
    int lane = tid & 31;
    int w    = tid >> 5;
    int g    = lane >> 2;
    int t    = lane & 3;
    int wrow = w * 16;

    int qb = blockIdx.x;
    int bh = blockIdx.y;
    int b  = bh >> 4;
    int h  = bh & (HH - 1);
    size_t head = (size_t)bh * SS * DKK;

    // ---- stage Q tile [64][64] as tf32 ----
#pragma unroll
    for (int it = 0; it < 8; it++) {
        int i  = it * 128 + tid;
        int r  = i >> 4;
        int c4 = (i & 15) << 2;
        float4 v4 = *(const float4*)&g_Q[head + (size_t)(qb * 64 + r) * DKK + c4];
        QPs[r][c4 + 0] = f2tf32(v4.x);
        QPs[r][c4 + 1] = f2tf32(v4.y);
        QPs[r][c4 + 2] = f2tf32(v4.z);
        QPs[r][c4 + 3] = f2tf32(v4.w);
    }
    __syncthreads();

    // ---- Q fragments to registers (A frags, 8 k-steps) ----
    unsigned qf[8][4];
#pragma unroll
    for (int ks = 0; ks < 8; ks++) {
        qf[ks][0] = QPs[wrow + g][ks * 8 + t];
        qf[ks][1] = QPs[wrow + g + 8][ks * 8 + t];
        qf[ks][2] = QPs[wrow + g][ks * 8 + t + 4];
        qf[ks][3] = QPs[wrow + g + 8][ks * 8 + t + 4];
    }

    float o[8][4];
#pragma unroll
    for (int nj = 0; nj < 8; nj++)
#pragma unroll
        for (int e = 0; e < 4; e++) o[nj][e] = 0.0f;
    float m0 = -1e30f, m1 = -1e30f, l0 = 0.0f, l1 = 0.0f;

    for (int j = 0; j <= qb; j++) {
        __syncthreads();   // also orders first P writes after all qf reads
        // ---- stage K,V tiles [64][64] ----
#pragma unroll
        for (int it = 0; it < 8; it++) {
            int i  = it * 128 + tid;
            int r  = i >> 4;
            int c4 = (i & 15) << 2;
            size_t gi = head + (size_t)(j * 64 + r) * DKK + c4;
            float4 kv = *(const float4*)&g_K[gi];
            Ks[r][c4 + 0] = f2tf32(kv.x);
            Ks[r][c4 + 1] = f2tf32(kv.y);
            Ks[r][c4 + 2] = f2tf32(kv.z);
            Ks[r][c4 + 3] = f2tf32(kv.w);
            float4 vv = *(const float4*)&g_V[gi];
            Vs[r][c4 + 0] = f2tf32(vv.x);
            Vs[r][c4 + 1] = f2tf32(vv.y);
            Vs[r][c4 + 2] = f2tf32(vv.z);
            Vs[r][c4 + 3] = f2tf32(vv.w);
        }
        __syncthreads();

        // ---- S = Q @ K^T ----
        float s[8][4];
#pragma unroll
        for (int nj = 0; nj < 8; nj++)
#pragma unroll
            for (int e = 0; e < 4; e++) s[nj][e] = 0.0f;

#pragma unroll
        for (int ks = 0; ks < 8; ks++) {
#pragma unroll
            for (int nj = 0; nj < 8; nj++) {
                unsigned bf[2];
                bf[0] = Ks[nj * 8 + g][ks * 8 + t];
                bf[1] = Ks[nj * 8 + g][ks * 8 + t + 4];
                mma_tf32(s[nj], qf[ks], bf);
            }
        }

        // ---- softmax (log2 domain) ----
#pragma unroll
        for (int nj = 0; nj < 8; nj++)
#pragma unroll
            for (int e = 0; e < 4; e++) s[nj][e] *= SCALE_LOG2E;

        if (j == qb) {  // diagonal tile: causal mask (local coords)
#pragma unroll
            for (int nj = 0; nj < 8; nj++) {
                int c0 = nj * 8 + 2 * t;
                if (c0     > wrow + g)     s[nj][0] = -1e30f;
                if (c0 + 1 > wrow + g)     s[nj][1] = -1e30f;
                if (c0     > wrow + g + 8) s[nj][2] = -1e30f;
                if (c0 + 1 > wrow + g + 8) s[nj][3] = -1e30f;
            }
        }

        float mx0 = -1e30f, mx1 = -1e30f;
#pragma unroll
        for (int nj = 0; nj < 8; nj++) {
            mx0 = fmaxf(mx0, fmaxf(s[nj][0], s[nj][1]));
            mx1 = fmaxf(mx1, fmaxf(s[nj][2], s[nj][3]));
        }
        mx0 = fmaxf(mx0, __shfl_xor_sync(0xffffffffu, mx0, 1));
        mx0 = fmaxf(mx0, __shfl_xor_sync(0xffffffffu, mx0, 2));
        mx1 = fmaxf(mx1, __shfl_xor_sync(0xffffffffu, mx1, 1));
        mx1 = fmaxf(mx1, __shfl_xor_sync(0xffffffffu, mx1, 2));

        float m0n = fmaxf(m0, mx0), m1n = fmaxf(m1, mx1);
        float a0 = ex2(m0 - m0n),   a1 = ex2(m1 - m1n);
        m0 = m0n; m1 = m1n;

        float rs0 = 0.0f, rs1 = 0.0f;
#pragma unroll
        for (int nj = 0; nj < 8; nj++) {
            float p;
            p = ex2(s[nj][0] - m0n); rs0 += p; s[nj][0] = p;
            p = ex2(s[nj][1] - m0n); rs0 += p; s[nj][1] = p;
            p = ex2(s[nj][2] - m1n); rs1 += p; s[nj][2] = p;
            p = ex2(s[nj][3] - m1n); rs1 += p; s[nj][3] = p;
        }
        rs0 += __shfl_xor_sync(0xffffffffu, rs0, 1);
        rs0 += __shfl_xor_sync(0xffffffffu, rs0, 2);
        rs1 += __shfl_xor_sync(0xffffffffu, rs1, 1);
        rs1 += __shfl_xor_sync(0xffffffffu, rs1, 2);

        l0 = l0 * a0 + rs0;
        l1 = l1 * a1 + rs1;
#pragma unroll
        for (int nj = 0; nj < 8; nj++) {
            o[nj][0] *= a0; o[nj][1] *= a0;
            o[nj][2] *= a1; o[nj][3] *= a1;
        }

        // ---- P -> smem (row-major, pad 68; warp-private rows) ----
#pragma unroll
        for (int nj = 0; nj < 8; nj++) {
            int cc = nj * 8 + 2 * t;
            QPs[wrow + g][cc]         = f2tf32(s[nj][0]);
            QPs[wrow + g][cc + 1]     = f2tf32(s[nj][1]);
            QPs[wrow + g + 8][cc]     = f2tf32(s[nj][2]);
            QPs[wrow + g + 8][cc + 1] = f2tf32(s[nj][3]);
        }
        __syncwarp();

        // ---- O += P @ V ----
#pragma unroll
        for (int ks = 0; ks < 8; ks++) {
            unsigned pf[4];
            pf[0] = QPs[wrow + g][ks * 8 + t];
            pf[1] = QPs[wrow + g + 8][ks * 8 + t];
            pf[2] = QPs[wrow + g][ks * 8 + t + 4];
            pf[3] = QPs[wrow + g + 8][ks * 8 + t + 4];
#pragma unroll
            for (int nj = 0; nj < 8; nj++) {
                unsigned vf[2];
                vf[0] = Vs[ks * 8 + t][nj * 8 + g];
                vf[1] = Vs[ks * 8 + t + 4][nj * 8 + g];
                mma_tf32(o[nj], pf, vf);
            }
        }
    }

    // ---- epilogue: normalize + write [B,S,D] ----
    float inv0 = 1.0f / l0, inv1 = 1.0f / l1;
    int row0 = qb * 64 + wrow + g;
    size_t base0 = ((size_t)(b * SS + row0)) * DD + h * 64;
    size_t base1 = base0 + (size_t)8 * DD;
#pragma unroll
    for (int nj = 0; nj < 8; nj++) {
        int cc = nj * 8 + 2 * t;
        *(float2*)&g_Ctx[base0 + cc] = make_float2(o[nj][0] * inv0, o[nj][1] * inv0);
        *(float2*)&g_Ctx[base1 + cc] = make_float2(o[nj][2] * inv1, o[nj][3] * inv1);
    }
}

// ---------------------------------------------------------------------------
// kernel_launch
// ---------------------------------------------------------------------------
extern "C" void kernel_launch(void* const* d_in, const int* in_sizes, int n_in,
                              void* d_out, int out_size)
{
    const float* q    = (const float*)d_in[0];
    const float* k    = (const float*)d_in[1];
    const float* v    = (const float*)d_in[2];
    const float* wq_w = (const float*)d_in[4];
    const float* wq_b = (const float*)d_in[5];
    const float* wk_w = (const float*)d_in[6];
    const float* wk_b = (const float*)d_in[7];
    const float* wv_w = (const float*)d_in[8];
    const float* wv_b = (const float*)d_in[9];
    const float* wo_w = (const float*)d_in[10];
    const float* wo_b = (const float*)d_in[11];
    float* out = (float*)d_out;

    dim3 gg(DD / 128, MM / 128);  // (8, 32)

    gemm_tf32_kernel<<<gg, 256>>>(q, wq_w, wq_b, nullptr, 1, 0);
    gemm_tf32_kernel<<<gg, 256>>>(k, wk_w, wk_b, nullptr, 2, 0);
    gemm_tf32_kernel<<<gg, 256>>>(v, wv_w, wv_b, nullptr, 3, 0);

    attn_tc_kernel<<<dim3(SS / 64, BB * HH), 128>>>();

    gemm_tf32_kernel<<<gg, 256>>>(nullptr, wo_w, wo_b, out, 0, 1);
}

// round 4
// speedup vs baseline: 3.2595x; 1.4806x over previous
#include <cuda_runtime.h>
#include <cuda_bf16.h>
#include <math.h>

// Problem constants
#define BB 2
#define SS 2048
#define DD 1024
#define HH 16
#define DKK 64
#define MM (BB * SS)   // 4096 rows for all GEMMs

// ---------------------------------------------------------------------------
// Scratch (device globals; no runtime allocation allowed)
// ---------------------------------------------------------------------------
__device__ float g_Q[BB * HH * SS * DKK];   // [B,H,S,DK]
__device__ float g_K[BB * HH * SS * DKK];
__device__ float g_V[BB * HH * SS * DKK];
__device__ float g_Ctx[BB * SS * DD];       // [B,S,D] attention output

// ---------------------------------------------------------------------------
// helpers
// ---------------------------------------------------------------------------
__device__ __forceinline__ unsigned f2tf32(float x) {
    unsigned y;
    asm("cvt.rna.tf32.f32 %0, %1;" : "=r"(y) : "f"(x));
    return y;
}

__device__ __forceinline__ float ex2(float x) {
    float y;
    asm("ex2.approx.f32 %0, %1;" : "=f"(y) : "f"(x));
    return y;
}

__device__ __forceinline__ void mma_tf32(float* c, const unsigned* a, const unsigned* b) {
    asm volatile("mma.sync.aligned.m16n8k8.row.col.f32.tf32.tf32.f32 "
        "{%0,%1,%2,%3}, {%4,%5,%6,%7}, {%8,%9}, {%0,%1,%2,%3};"
        : "+f"(c[0]), "+f"(c[1]), "+f"(c[2]), "+f"(c[3])
        : "r"(a[0]), "r"(a[1]), "r"(a[2]), "r"(a[3]), "r"(b[0]), "r"(b[1]));
}

__device__ __forceinline__ void cp_async16(void* smem_dst, const void* gmem_src) {
    unsigned s = (unsigned)__cvta_generic_to_shared(smem_dst);
    asm volatile("cp.async.cg.shared.global [%0], [%1], 16;" :: "r"(s), "l"(gmem_src));
}
__device__ __forceinline__ void cp_commit() {
    asm volatile("cp.async.commit_group;");
}
template <int N> __device__ __forceinline__ void cp_wait() {
    asm volatile("cp.async.wait_group %0;" :: "n"(N));
}

// ---------------------------------------------------------------------------
// Pipelined NT GEMM via tf32 tensor cores:
//   C[m,n] = sum_k Ain[m,k] * W[n,k] + bias[n]
// M=4096, N=1024, K=1024. BM=BN=128, BK=16, 3-stage cp.async ring.
// 256 threads (8 warps, 2x4); each warp 64x32 subtile = 4x4 m16n8k8 atoms.
// blockIdx.z selects one of up to 3 (A, W, bias, out_mode) problem instances.
// out_mode: 0 -> C[m*N+n]; 1/2/3 -> scatter to g_Q/g_K/g_V [B,H,S,DK]
// smem rows padded to 20 words: fragment LDS banks (20g+t)%32 all distinct.
// ---------------------------------------------------------------------------
#define RS 20           // smem row stride (floats)
#define STG 3           // pipeline stages
#define KT (DD / 16)    // 64 k-tiles

struct GemmArgs {
    const float* A[3];
    const float* W[3];
    const float* bias[3];
    float* C;
    int out_mode[3];   // 0 plain, 1/2/3 scatter QKV
};

__global__ __launch_bounds__(256, 2) void gemm_pipe_kernel(GemmArgs args)
{
    __shared__ float As[STG][128 * RS];
    __shared__ float Bs[STG][128 * RS];

    int z = blockIdx.z;
    const float* __restrict__ Ain  = args.A[z];
    const float* __restrict__ W    = args.W[z];
    const float* __restrict__ bias = args.bias[z];
    int out_mode = args.out_mode[z];

    int tid  = threadIdx.x;
    int lane = tid & 31;
    int w    = tid >> 5;
    int wm   = w >> 2;          // 0..1
    int wn   = w & 3;           // 0..3
    int g    = lane >> 2;       // 0..7
    int t    = lane & 3;        // 0..3

    int bm = blockIdx.y * 128;
    int bn = blockIdx.x * 128;

    // each thread stages 2 16B-chunks of A and 2 of B per k-tile
    int r0c = tid >> 1;                 // 0..127
    int c0c = (tid & 1) * 8;            // 0 or 8  (two float4 at +0,+4)

    float c[4][4][4];
#pragma unroll
    for (int mi = 0; mi < 4; mi++)
#pragma unroll
        for (int nj = 0; nj < 4; nj++)
#pragma unroll
            for (int e = 0; e < 4; e++) c[mi][nj][e] = 0.0f;

    // ---- prefetch stages 0..STG-2 ----
#pragma unroll
    for (int pf = 0; pf < STG - 1; pf++) {
        int k0 = pf * 16;
        cp_async16(&As[pf][r0c * RS + c0c],     &Ain[(size_t)(bm + r0c) * DD + k0 + c0c]);
        cp_async16(&As[pf][r0c * RS + c0c + 4], &Ain[(size_t)(bm + r0c) * DD + k0 + c0c + 4]);
        cp_async16(&Bs[pf][r0c * RS + c0c],     &W[(size_t)(bn + r0c) * DD + k0 + c0c]);
        cp_async16(&Bs[pf][r0c * RS + c0c + 4], &W[(size_t)(bn + r0c) * DD + k0 + c0c + 4]);
        cp_commit();
    }
    cp_wait<STG - 2>();
    __syncthreads();

    for (int kt = 0; kt < KT; kt++) {
        int st = kt % STG;

        // ---- prefetch k-tile kt+STG-1 into the stage just freed ----
        if (kt + STG - 1 < KT) {
            int ps = (kt + STG - 1) % STG;
            int k0 = (kt + STG - 1) * 16;
            cp_async16(&As[ps][r0c * RS + c0c],     &Ain[(size_t)(bm + r0c) * DD + k0 + c0c]);
            cp_async16(&As[ps][r0c * RS + c0c + 4], &Ain[(size_t)(bm + r0c) * DD + k0 + c0c + 4]);
            cp_async16(&Bs[ps][r0c * RS + c0c],     &W[(size_t)(bn + r0c) * DD + k0 + c0c]);
            cp_async16(&Bs[ps][r0c * RS + c0c + 4], &W[(size_t)(bn + r0c) * DD + k0 + c0c + 4]);
        }
        cp_commit();

        // ---- compute on stage st ----
        const float* a_s = As[st];
        const float* b_s = Bs[st];
#pragma unroll
        for (int ks = 0; ks < 2; ks++) {
            unsigned af[4][4], bf[4][2];
#pragma unroll
            for (int mi = 0; mi < 4; mi++) {
                int m = wm * 64 + mi * 16 + g;
                af[mi][0] = f2tf32(a_s[m * RS + ks * 8 + t]);
                af[mi][1] = f2tf32(a_s[(m + 8) * RS + ks * 8 + t]);
                af[mi][2] = f2tf32(a_s[m * RS + ks * 8 + t + 4]);
                af[mi][3] = f2tf32(a_s[(m + 8) * RS + ks * 8 + t + 4]);
            }
#pragma unroll
            for (int nj = 0; nj < 4; nj++) {
                int n = wn * 32 + nj * 8 + g;
                bf[nj][0] = f2tf32(b_s[n * RS + ks * 8 + t]);
                bf[nj][1] = f2tf32(b_s[n * RS + ks * 8 + t + 4]);
            }
#pragma unroll
            for (int mi = 0; mi < 4; mi++)
#pragma unroll
                for (int nj = 0; nj < 4; nj++)
                    mma_tf32(c[mi][nj], af[mi], bf[nj]);
        }

        // ---- advance pipeline: next stage must be resident ----
        cp_wait<STG - 2>();
        __syncthreads();
    }

    // ---- epilogue: bias + store ----
#pragma unroll
    for (int mi = 0; mi < 4; mi++) {
#pragma unroll
        for (int nj = 0; nj < 4; nj++) {
            int m = bm + wm * 64 + mi * 16 + g;
            int n = bn + wn * 32 + nj * 8 + 2 * t;
            float b0 = bias[n], b1 = bias[n + 1];
            float2 v0 = make_float2(c[mi][nj][0] + b0, c[mi][nj][1] + b1);
            float2 v1 = make_float2(c[mi][nj][2] + b0, c[mi][nj][3] + b1);
            if (out_mode == 0) {
                *(float2*)&args.C[(size_t)m * DD + n]       = v0;
                *(float2*)&args.C[(size_t)(m + 8) * DD + n] = v1;
            } else {
                int b  = m >> 11;
                int s  = m & (SS - 1);
                int h  = n >> 6;
                int dk = n & (DKK - 1);
                float* dst = (out_mode == 1) ? g_Q : (out_mode == 2) ? g_K : g_V;
                size_t base = (((size_t)(b * HH + h)) * SS) * DKK + dk;
                *(float2*)&dst[base + (size_t)s * DKK]  = v0;
                int s1 = (m + 8) & (SS - 1);
                *(float2*)&dst[base + (size_t)s1 * DKK] = v1;
            }
        }
    }
}

// ---------------------------------------------------------------------------
// Causal flash attention via tf32 tensor cores (unchanged from R2).
// ---------------------------------------------------------------------------
#define SCALE_LOG2E 0.1803368801111244f   // (1/sqrt(64)) * log2(e)

__global__ __launch_bounds__(128) void attn_tc_kernel()
{
    __shared__ unsigned QPs[64][68];
    __shared__ unsigned Ks[64][68];
    __shared__ unsigned Vs[64][72];

    int tid  = threadIdx.x;
    int lane = tid & 31;
    int w    = tid >> 5;
    int g    = lane >> 2;
    int t    = lane & 3;
    int wrow = w * 16;

    int qb = blockIdx.x;
    int bh = blockIdx.y;
    int b  = bh >> 4;
    int h  = bh & (HH - 1);
    size_t head = (size_t)bh * SS * DKK;

#pragma unroll
    for (int it = 0; it < 8; it++) {
        int i  = it * 128 + tid;
        int r  = i >> 4;
        int c4 = (i & 15) << 2;
        float4 v4 = *(const float4*)&g_Q[head + (size_t)(qb * 64 + r) * DKK + c4];
        QPs[r][c4 + 0] = f2tf32(v4.x);
        QPs[r][c4 + 1] = f2tf32(v4.y);
        QPs[r][c4 + 2] = f2tf32(v4.z);
        QPs[r][c4 + 3] = f2tf32(v4.w);
    }
    __syncthreads();

    unsigned qf[8][4];
#pragma unroll
    for (int ks = 0; ks < 8; ks++) {
        qf[ks][0] = QPs[wrow + g][ks * 8 + t];
        qf[ks][1] = QPs[wrow + g + 8][ks * 8 + t];
        qf[ks][2] = QPs[wrow + g][ks * 8 + t + 4];
        qf[ks][3] = QPs[wrow + g + 8][ks * 8 + t + 4];
    }

    float o[8][4];
#pragma unroll
    for (int nj = 0; nj < 8; nj++)
#pragma unroll
        for (int e = 0; e < 4; e++) o[nj][e] = 0.0f;
    float m0 = -1e30f, m1 = -1e30f, l0 = 0.0f, l1 = 0.0f;

    for (int j = 0; j <= qb; j++) {
        __syncthreads();
#pragma unroll
        for (int it = 0; it < 8; it++) {
            int i  = it * 128 + tid;
            int r  = i >> 4;
            int c4 = (i & 15) << 2;
            size_t gi = head + (size_t)(j * 64 + r) * DKK + c4;
            float4 kv = *(const float4*)&g_K[gi];
            Ks[r][c4 + 0] = f2tf32(kv.x);
            Ks[r][c4 + 1] = f2tf32(kv.y);
            Ks[r][c4 + 2] = f2tf32(kv.z);
            Ks[r][c4 + 3] = f2tf32(kv.w);
            float4 vv = *(const float4*)&g_V[gi];
            Vs[r][c4 + 0] = f2tf32(vv.x);
            Vs[r][c4 + 1] = f2tf32(vv.y);
            Vs[r][c4 + 2] = f2tf32(vv.z);
            Vs[r][c4 + 3] = f2tf32(vv.w);
        }
        __syncthreads();

        float s[8][4];
#pragma unroll
        for (int nj = 0; nj < 8; nj++)
#pragma unroll
            for (int e = 0; e < 4; e++) s[nj][e] = 0.0f;

#pragma unroll
        for (int ks = 0; ks < 8; ks++) {
#pragma unroll
            for (int nj = 0; nj < 8; nj++) {
                unsigned bf[2];
                bf[0] = Ks[nj * 8 + g][ks * 8 + t];
                bf[1] = Ks[nj * 8 + g][ks * 8 + t + 4];
                mma_tf32(s[nj], qf[ks], bf);
            }
        }

#pragma unroll
        for (int nj = 0; nj < 8; nj++)
#pragma unroll
            for (int e = 0; e < 4; e++) s[nj][e] *= SCALE_LOG2E;

        if (j == qb) {
#pragma unroll
            for (int nj = 0; nj < 8; nj++) {
                int c0 = nj * 8 + 2 * t;
                if (c0     > wrow + g)     s[nj][0] = -1e30f;
                if (c0 + 1 > wrow + g)     s[nj][1] = -1e30f;
                if (c0     > wrow + g + 8) s[nj][2] = -1e30f;
                if (c0 + 1 > wrow + g + 8) s[nj][3] = -1e30f;
            }
        }

        float mx0 = -1e30f, mx1 = -1e30f;
#pragma unroll
        for (int nj = 0; nj < 8; nj++) {
            mx0 = fmaxf(mx0, fmaxf(s[nj][0], s[nj][1]));
            mx1 = fmaxf(mx1, fmaxf(s[nj][2], s[nj][3]));
        }
        mx0 = fmaxf(mx0, __shfl_xor_sync(0xffffffffu, mx0, 1));
        mx0 = fmaxf(mx0, __shfl_xor_sync(0xffffffffu, mx0, 2));
        mx1 = fmaxf(mx1, __shfl_xor_sync(0xffffffffu, mx1, 1));
        mx1 = fmaxf(mx1, __shfl_xor_sync(0xffffffffu, mx1, 2));

        float m0n = fmaxf(m0, mx0), m1n = fmaxf(m1, mx1);
        float a0 = ex2(m0 - m0n),   a1 = ex2(m1 - m1n);
        m0 = m0n; m1 = m1n;

        float rs0 = 0.0f, rs1 = 0.0f;
#pragma unroll
        for (int nj = 0; nj < 8; nj++) {
            float p;
            p = ex2(s[nj][0] - m0n); rs0 += p; s[nj][0] = p;
            p = ex2(s[nj][1] - m0n); rs0 += p; s[nj][1] = p;
            p = ex2(s[nj][2] - m1n); rs1 += p; s[nj][2] = p;
            p = ex2(s[nj][3] - m1n); rs1 += p; s[nj][3] = p;
        }
        rs0 += __shfl_xor_sync(0xffffffffu, rs0, 1);
        rs0 += __shfl_xor_sync(0xffffffffu, rs0, 2);
        rs1 += __shfl_xor_sync(0xffffffffu, rs1, 1);
        rs1 += __shfl_xor_sync(0xffffffffu, rs1, 2);

        l0 = l0 * a0 + rs0;
        l1 = l1 * a1 + rs1;
#pragma unroll
        for (int nj = 0; nj < 8; nj++) {
            o[nj][0] *= a0; o[nj][1] *= a0;
            o[nj][2] *= a1; o[nj][3] *= a1;
        }

#pragma unroll
        for (int nj = 0; nj < 8; nj++) {
            int cc = nj * 8 + 2 * t;
            QPs[wrow + g][cc]         = f2tf32(s[nj][0]);
            QPs[wrow + g][cc + 1]     = f2tf32(s[nj][1]);
            QPs[wrow + g + 8][cc]     = f2tf32(s[nj][2]);
            QPs[wrow + g + 8][cc + 1] = f2tf32(s[nj][3]);
        }
        __syncwarp();

#pragma unroll
        for (int ks = 0; ks < 8; ks++) {
            unsigned pf[4];
            pf[0] = QPs[wrow + g][ks * 8 + t];
            pf[1] = QPs[wrow + g + 8][ks * 8 + t];
            pf[2] = QPs[wrow + g][ks * 8 + t + 4];
            pf[3] = QPs[wrow + g + 8][ks * 8 + t + 4];
#pragma unroll
            for (int nj = 0; nj < 8; nj++) {
                unsigned vf[2];
                vf[0] = Vs[ks * 8 + t][nj * 8 + g];
                vf[1] = Vs[ks * 8 + t + 4][nj * 8 + g];
                mma_tf32(o[nj], pf, vf);
            }
        }
    }

    float inv0 = 1.0f / l0, inv1 = 1.0f / l1;
    int row0 = qb * 64 + wrow + g;
    size_t base0 = ((size_t)(b * SS + row0)) * DD + h * 64;
    size_t base1 = base0 + (size_t)8 * DD;
#pragma unroll
    for (int nj = 0; nj < 8; nj++) {
        int cc = nj * 8 + 2 * t;
        *(float2*)&g_Ctx[base0 + cc] = make_float2(o[nj][0] * inv0, o[nj][1] * inv0);
        *(float2*)&g_Ctx[base1 + cc] = make_float2(o[nj][2] * inv1, o[nj][3] * inv1);
    }
}

// ---------------------------------------------------------------------------
// kernel_launch
// ---------------------------------------------------------------------------
extern "C" void kernel_launch(void* const* d_in, const int* in_sizes, int n_in,
                              void* d_out, int out_size)
{
    const float* q    = (const float*)d_in[0];
    const float* k    = (const float*)d_in[1];
    const float* v    = (const float*)d_in[2];
    const float* wq_w = (const float*)d_in[4];
    const float* wq_b = (const float*)d_in[5];
    const float* wk_w = (const float*)d_in[6];
    const float* wk_b = (const float*)d_in[7];
    const float* wv_w = (const float*)d_in[8];
    const float* wv_b = (const float*)d_in[9];
    const float* wo_w = (const float*)d_in[10];
    const float* wo_b = (const float*)d_in[11];
    float* out = (float*)d_out;

    // fused QKV projections: one launch, 3 GEMMs stacked on z (wave packing)
    GemmArgs qkv;
    qkv.A[0] = q;    qkv.A[1] = k;    qkv.A[2] = v;
    qkv.W[0] = wq_w; qkv.W[1] = wk_w; qkv.W[2] = wv_w;
    qkv.bias[0] = wq_b; qkv.bias[1] = wk_b; qkv.bias[2] = wv_b;
    qkv.C = nullptr;
    qkv.out_mode[0] = 1; qkv.out_mode[1] = 2; qkv.out_mode[2] = 3;
    gemm_pipe_kernel<<<dim3(DD / 128, MM / 128, 3), 256>>>(qkv);

    attn_tc_kernel<<<dim3(SS / 64, BB * HH), 128>>>();

    // output projection (A = g_Ctx via device-global path: pass nullptr A and
    // read g_Ctx? -> simply pass the device-global address is not accessible
    // host-side; instead reuse args with A pointing to g_Ctx via a device copy)
    GemmArgs og;
    // g_Ctx address must be taken on device; use cudaGetSymbolAddress once per
    // call (cheap, not an allocation, graph-capture safe since it's host-side).
    void* ctx_ptr = nullptr;
    cudaGetSymbolAddress(&ctx_ptr, g_Ctx);
    og.A[0] = (const float*)ctx_ptr; og.A[1] = og.A[0]; og.A[2] = og.A[0];
    og.W[0] = wo_w; og.W[1] = wo_w; og.W[2] = wo_w;
    og.bias[0] = wo_b; og.bias[1] = wo_b; og.bias[2] = wo_b;
    og.C = out;
    og.out_mode[0] = 0; og.out_mode[1] = 0; og.out_mode[2] = 0;
    gemm_pipe_kernel<<<dim3(DD / 128, MM / 128, 1), 256>>>(og);
}